// round 1
// baseline (speedup 1.0000x reference)
#include <cuda_runtime.h>

// NeRF volume-rendering aggregation.
// Shapes: raw (NR,128,4) f32, z (NR,128) f32, rays_d (NR,3) f32, bg (3) f32
// Outputs (concatenated, tuple order):
//   rgb_map (NR,3), depth_map (NR), disparity_map (NR), alpha_map (NR), weights (NR,128)
//
// One warp per ray. 4 rounds of 32 consecutive points; warp product-scan for
// the exclusive cumulative transmittance, scalar carry across rounds.

#define FARV 1e10f
#define EPSV 1e-10f

__global__ __launch_bounds__(256) void nerf_agg_kernel(
    const float4* __restrict__ raw,    // (NR, 128) of float4
    const float*  __restrict__ z,      // (NR, 128)
    const float*  __restrict__ rays_d, // (NR, 3)
    const float*  __restrict__ bg,     // (3)
    float* __restrict__ out_rgb,       // (NR, 3)
    float* __restrict__ out_depth,     // (NR)
    float* __restrict__ out_disp,      // (NR)
    float* __restrict__ out_alpha,     // (NR)
    float* __restrict__ out_w,         // (NR, 128)
    int nrays)
{
    const int warp = threadIdx.x >> 5;
    const int lane = threadIdx.x & 31;
    const int ray  = blockIdx.x * 8 + warp;
    if (ray >= nrays) return;   // warp-uniform exit

    const float4* rawr = raw + (size_t)ray * 128;
    const float*  zr   = z   + (size_t)ray * 128;

    // ray-direction norm (lane-uniform broadcast loads)
    const float dx = rays_d[ray * 3 + 0];
    const float dy = rays_d[ray * 3 + 1];
    const float dz = rays_d[ray * 3 + 2];
    const float nrm = sqrtf(dx * dx + dy * dy + dz * dz);

    float carry = 1.0f;                 // running transmittance across rounds
    float ar = 0.f, ag = 0.f, ab = 0.f; // rgb accumulators
    float aa = 0.f, ad = 0.f;           // alpha / depth accumulators

#pragma unroll
    for (int rr = 0; rr < 4; rr++) {
        const int p = rr * 32 + lane;

        const float4 rv = rawr[p];
        const float  zp = zr[p];

        // distance to next sample; last sample -> FAR. Scaled by |rays_d|.
        float d;
        if (p == 127) d = FARV;
        else          d = zr[p + 1] - zp;
        d *= nrm;

        // 3 sigmoids with a single shared rcp:
        //   s_i = 1/(1+e_i) = rcp(a0*a1*a2) * (prod of the other two)
        const float e0 = __expf(-rv.x);
        const float e1 = __expf(-rv.y);
        const float e2 = __expf(-rv.z);
        const float a0 = 1.0f + e0, a1 = 1.0f + e1, a2 = 1.0f + e2;
        const float a12 = a1 * a2;
        float inv;
        asm("rcp.approx.f32 %0, %1;" : "=f"(inv) : "f"(a0 * a12));
        const float s0 = inv * a12;
        const float s1 = inv * (a0 * a2);
        const float s2 = inv * (a0 * a1);

        // alpha = 1 - exp(-relu(sigma) * d)
        const float sg    = fmaxf(rv.w, 0.0f);
        const float alpha = 1.0f - __expf(-sg * d);
        const float t     = 1.0f - alpha + EPSV;

        // inclusive warp product-scan of t
        float prod = t;
#pragma unroll
        for (int off = 1; off < 32; off <<= 1) {
            const float v = __shfl_up_sync(0xffffffffu, prod, off);
            if (lane >= off) prod *= v;
        }
        // exclusive prefix
        float excl = __shfl_up_sync(0xffffffffu, prod, 1);
        if (lane == 0) excl = 1.0f;

        const float w = alpha * (carry * excl);
        carry *= __shfl_sync(0xffffffffu, prod, 31);

        ar = fmaf(w, s0, ar);
        ag = fmaf(w, s1, ag);
        ab = fmaf(w, s2, ab);
        aa += w;
        ad = fmaf(w, zp, ad);

        out_w[(size_t)ray * 128 + p] = w;   // coalesced 128B store
    }

    // warp tree-reduce the 5 scalars
#pragma unroll
    for (int off = 16; off >= 1; off >>= 1) {
        ar += __shfl_xor_sync(0xffffffffu, ar, off);
        ag += __shfl_xor_sync(0xffffffffu, ag, off);
        ab += __shfl_xor_sync(0xffffffffu, ab, off);
        aa += __shfl_xor_sync(0xffffffffu, aa, off);
        ad += __shfl_xor_sync(0xffffffffu, ad, off);
    }

    if (lane == 0) {
        const float b0 = bg[0], b1 = bg[1], b2 = bg[2];
        const bool is_bg = (b0 >= 0.f && b0 <= 1.f &&
                            b1 >= 0.f && b1 <= 1.f &&
                            b2 >= 0.f && b2 <= 1.f);
        if (is_bg) {
            const float m = 1.0f - aa;
            ar = fmaf(m, b0, ar);
            ag = fmaf(m, b1, ag);
            ab = fmaf(m, b2, ab);
        }
        out_rgb[ray * 3 + 0] = ar;
        out_rgb[ray * 3 + 1] = ag;
        out_rgb[ray * 3 + 2] = ab;
        out_depth[ray] = ad;
        out_alpha[ray] = aa;

        // disparity = 1 / (relu(depth/alpha - EPS) + EPS)  (precise divides; per-ray only)
        const float q = ad / aa;
        out_disp[ray] = 1.0f / (fmaxf(q - EPSV, 0.0f) + EPSV);
    }
}

extern "C" void kernel_launch(void* const* d_in, const int* in_sizes, int n_in,
                              void* d_out, int out_size)
{
    const float* raw = (const float*)d_in[0];  // (B,R,P,4)
    const float* zv  = (const float*)d_in[1];  // (B,R,P)
    const float* rd  = (const float*)d_in[2];  // (B,R,3)
    const float* bg  = (const float*)d_in[3];  // (3)

    const int nrays = in_sizes[1] / 128;       // B*R

    float* out       = (float*)d_out;
    float* out_rgb   = out;
    float* out_depth = out + (size_t)nrays * 3;
    float* out_disp  = out + (size_t)nrays * 4;
    float* out_alpha = out + (size_t)nrays * 5;
    float* out_w     = out + (size_t)nrays * 6;

    const int blocks = (nrays + 7) / 8;        // 8 warps (rays) per 256-thread block
    nerf_agg_kernel<<<blocks, 256>>>((const float4*)raw, zv, rd, bg,
                                     out_rgb, out_depth, out_disp, out_alpha,
                                     out_w, nrays);
}

// round 2
// speedup vs baseline: 1.0914x; 1.0914x over previous
#include <cuda_runtime.h>

// NeRF volume-rendering aggregation — R2.
// Changes vs R1:
//  - sigmoids via tanh.approx.f32 (1 MUFU each) instead of EX2+shared RCP:
//    MUFU ops/point 5 -> 4 (the binding pipe).
//  - the 4 per-round product scans run interleaved (independent), only the
//    round totals are chained: exposed SHFL latency /ray ~520 -> ~140 cyc.

#define FARV 1e10f
#define EPSV 1e-10f

__device__ __forceinline__ float fast_tanh(float x) {
    float r;
    asm("tanh.approx.f32 %0, %1;" : "=f"(r) : "f"(x));
    return r;
}

__global__ __launch_bounds__(256) void nerf_agg_kernel(
    const float4* __restrict__ raw,    // (NR, 128) of float4
    const float*  __restrict__ z,      // (NR, 128)
    const float*  __restrict__ rays_d, // (NR, 3)
    const float*  __restrict__ bg,     // (3)
    float* __restrict__ out_rgb,       // (NR, 3)
    float* __restrict__ out_depth,     // (NR)
    float* __restrict__ out_disp,      // (NR)
    float* __restrict__ out_alpha,     // (NR)
    float* __restrict__ out_w,         // (NR, 128)
    int nrays)
{
    const int warp = threadIdx.x >> 5;
    const int lane = threadIdx.x & 31;
    const int ray  = blockIdx.x * 8 + warp;
    if (ray >= nrays) return;   // warp-uniform exit

    const float4* rawr = raw + (size_t)ray * 128;
    const float*  zr   = z   + (size_t)ray * 128;

    // ray-direction norm (lane-uniform broadcast loads)
    const float dx = rays_d[ray * 3 + 0];
    const float dy = rays_d[ray * 3 + 1];
    const float dz = rays_d[ray * 3 + 2];
    const float nrm = sqrtf(dx * dx + dy * dy + dz * dz);

    // ---- Phase A: batched loads (max MLP) ----
    float4 rv[4];
    float  zp[4], zn[4];
#pragma unroll
    for (int rr = 0; rr < 4; rr++) {
        const int p = rr * 32 + lane;
        rv[rr] = rawr[p];
        zp[rr] = zr[p];
        zn[rr] = (p == 127) ? 0.0f : zr[p + 1];  // value unused for p==127
    }

    // ---- Phase B: alpha / transmittance factor per round (independent MUFU) ----
    float alpha[4], prod[4];
#pragma unroll
    for (int rr = 0; rr < 4; rr++) {
        const int p = rr * 32 + lane;
        float d = (p == 127) ? FARV : (zn[rr] - zp[rr]);
        d *= nrm;
        const float sg = fmaxf(rv[rr].w, 0.0f);
        const float ex = __expf(-sg * d);     // FMUL + MUFU.EX2
        alpha[rr] = 1.0f - ex;
        prod[rr]  = ex + EPSV;                // t = 1 - alpha + EPS
    }

    // ---- Phase C: 4 interleaved inclusive product scans ----
#pragma unroll
    for (int off = 1; off < 32; off <<= 1) {
        const float v0 = __shfl_up_sync(0xffffffffu, prod[0], off);
        const float v1 = __shfl_up_sync(0xffffffffu, prod[1], off);
        const float v2 = __shfl_up_sync(0xffffffffu, prod[2], off);
        const float v3 = __shfl_up_sync(0xffffffffu, prod[3], off);
        if (lane >= off) {
            prod[0] *= v0; prod[1] *= v1; prod[2] *= v2; prod[3] *= v3;
        }
    }

    // round totals and carries (tiny serial combine)
    const float P0 = __shfl_sync(0xffffffffu, prod[0], 31);
    const float P1 = __shfl_sync(0xffffffffu, prod[1], 31);
    const float P2 = __shfl_sync(0xffffffffu, prod[2], 31);
    float carry[4];
    carry[0] = 1.0f;
    carry[1] = P0;
    carry[2] = P0 * P1;
    carry[3] = carry[2] * P2;

    // ---- Phase D: weights, sigmoids (tanh.approx), accumulate, store ----
    float ar = 0.f, ag = 0.f, ab = 0.f, aa = 0.f, ad = 0.f;
#pragma unroll
    for (int rr = 0; rr < 4; rr++) {
        float excl = __shfl_up_sync(0xffffffffu, prod[rr], 1);
        if (lane == 0) excl = 1.0f;
        const float w = alpha[rr] * (carry[rr] * excl);

        // sigmoid(x) = 0.5*tanh(0.5x) + 0.5   (1 MUFU each)
        const float s0 = fmaf(0.5f, fast_tanh(0.5f * rv[rr].x), 0.5f);
        const float s1 = fmaf(0.5f, fast_tanh(0.5f * rv[rr].y), 0.5f);
        const float s2 = fmaf(0.5f, fast_tanh(0.5f * rv[rr].z), 0.5f);

        ar = fmaf(w, s0, ar);
        ag = fmaf(w, s1, ag);
        ab = fmaf(w, s2, ab);
        aa += w;
        ad = fmaf(w, zp[rr], ad);

        out_w[(size_t)ray * 128 + rr * 32 + lane] = w;   // coalesced 128B store
    }

    // ---- warp tree-reduce the 5 scalars ----
#pragma unroll
    for (int off = 16; off >= 1; off >>= 1) {
        ar += __shfl_xor_sync(0xffffffffu, ar, off);
        ag += __shfl_xor_sync(0xffffffffu, ag, off);
        ab += __shfl_xor_sync(0xffffffffu, ab, off);
        aa += __shfl_xor_sync(0xffffffffu, aa, off);
        ad += __shfl_xor_sync(0xffffffffu, ad, off);
    }

    if (lane == 0) {
        const float b0 = bg[0], b1 = bg[1], b2 = bg[2];
        const bool is_bg = (b0 >= 0.f && b0 <= 1.f &&
                            b1 >= 0.f && b1 <= 1.f &&
                            b2 >= 0.f && b2 <= 1.f);
        if (is_bg) {
            const float m = 1.0f - aa;
            ar = fmaf(m, b0, ar);
            ag = fmaf(m, b1, ag);
            ab = fmaf(m, b2, ab);
        }
        out_rgb[ray * 3 + 0] = ar;
        out_rgb[ray * 3 + 1] = ag;
        out_rgb[ray * 3 + 2] = ab;
        out_depth[ray] = ad;
        out_alpha[ray] = aa;

        // disparity = 1 / (relu(depth/alpha - EPS) + EPS)  (precise divides; per-ray only)
        const float q = ad / aa;
        out_disp[ray] = 1.0f / (fmaxf(q - EPSV, 0.0f) + EPSV);
    }
}

extern "C" void kernel_launch(void* const* d_in, const int* in_sizes, int n_in,
                              void* d_out, int out_size)
{
    const float* raw = (const float*)d_in[0];  // (B,R,P,4)
    const float* zv  = (const float*)d_in[1];  // (B,R,P)
    const float* rd  = (const float*)d_in[2];  // (B,R,3)
    const float* bg  = (const float*)d_in[3];  // (3)

    const int nrays = in_sizes[1] / 128;       // B*R

    float* out       = (float*)d_out;
    float* out_rgb   = out;
    float* out_depth = out + (size_t)nrays * 3;
    float* out_disp  = out + (size_t)nrays * 4;
    float* out_alpha = out + (size_t)nrays * 5;
    float* out_w     = out + (size_t)nrays * 6;

    const int blocks = (nrays + 7) / 8;        // 8 warps (rays) per 256-thread block
    nerf_agg_kernel<<<blocks, 256>>>((const float4*)raw, zv, rd, bg,
                                     out_rgb, out_depth, out_disp, out_alpha,
                                     out_w, nrays);
}